// round 15
// baseline (speedup 1.0000x reference)
#include <cuda_runtime.h>
#include <math.h>

#define QN 4000
#define GN 100
#define BN 32
#define TPB 1024

// ---------------- device scratch (no allocs allowed) ----------------
__device__ unsigned       g_rowbits[BN][QN * 4];
__device__ unsigned short g_addc[BN][QN];
__device__ int            g_dk[BN][GN];
__device__ int            g_pos[BN][GN * 5];
__device__ float          g_costT[BN][GN][QN];   // transposed cost (column-major)

// ---------------------------------------------------------------------------
__device__ __forceinline__ float focal_fc(float x) {
    float p = 1.0f / (1.0f + expf(-x));
    float pos = 0.25f * (1.0f - p) * (1.0f - p) * (-logf(p + 1e-8f));
    float neg = 0.75f * p * p * (-logf(1.0f - p + 1e-8f));
    return pos - neg;
}

// reference's iterative "+100000.0" with per-step float rounding
__device__ __forceinline__ float apply_adds(float v, int a) {
    for (int i = 0; i < a; i++) v += 100000.0f;
    return v;
}

// ---------------------------------------------------------------------------
// Kernel 1: cost[B,Q,G] row-major into output + transposed copy into g_costT
// ---------------------------------------------------------------------------
__global__ void cost_kernel(const float* __restrict__ l1,
                            const float* __restrict__ l2,
                            const float* __restrict__ l3,
                            const float* __restrict__ pbx,
                            const float* __restrict__ gbx,
                            const float* __restrict__ iszg,
                            const int*  __restrict__ t1,
                            const int*  __restrict__ t2,
                            const int*  __restrict__ t3,
                            float* __restrict__ costOut)
{
    const int b   = blockIdx.y;
    const int tid = threadIdx.x;
    const int q   = blockIdx.x * 128 + tid;

    __shared__ float s_g[GN][4];
    __shared__ float s_bb[GN][4];
    __shared__ float s_cb[GN][4];
    __shared__ float s_ng[GN][4];
    __shared__ float s_ab[GN];
    __shared__ int   s_t1[GN], s_t2[GN], s_t3[GN];
    __shared__ float s_isz[4];
    __shared__ float s_fc[128][45];

    if (tid < GN) {
        const float* g4 = gbx + ((size_t)b * GN + tid) * 4;
        float gx0 = g4[0], gy0 = g4[1], gx1 = g4[2], gy1 = g4[3];
        s_g[tid][0] = gx0; s_g[tid][1] = gy0; s_g[tid][2] = gx1; s_g[tid][3] = gy1;
        float gcx = (gx0 + gx1) * 0.5f, gcy = (gy0 + gy1) * 0.5f;
        float gw = gx1 - gx0, gh = gy1 - gy0;
        float bx0 = gcx - 0.5f * gw, by0 = gcy - 0.5f * gh;
        float bx1 = gcx + 0.5f * gw, by1 = gcy + 0.5f * gh;
        s_bb[tid][0] = bx0; s_bb[tid][1] = by0; s_bb[tid][2] = bx1; s_bb[tid][3] = by1;
        float w2 = bx1 - bx0, h2 = by1 - by0;
        s_cb[tid][0] = gcx - 2.5f * w2; s_cb[tid][1] = gcx + 2.5f * w2;
        s_cb[tid][2] = gcy - 2.5f * h2; s_cb[tid][3] = gcy + 2.5f * h2;
        s_ab[tid] = (gx1 - gx0) * (gy1 - gy0);
        const float* is = iszg + (size_t)b * 4;
        s_ng[tid][0] = gx0 / is[0]; s_ng[tid][1] = gy0 / is[1];
        s_ng[tid][2] = gx1 / is[2]; s_ng[tid][3] = gy1 / is[3];
        s_t1[tid] = t1[b * GN + tid];
        s_t2[tid] = t2[b * GN + tid];
        s_t3[tid] = t3[b * GN + tid];
    }
    if (tid < 4) s_isz[tid] = iszg[(size_t)b * 4 + tid];

    const bool qv = (q < QN);
    if (qv) {
        const float* p1 = l1 + ((size_t)b * QN + q) * 4;
        #pragma unroll
        for (int c = 0; c < 4; c++)  s_fc[tid][c]      = focal_fc(p1[c]);
        const float* p2 = l2 + ((size_t)b * QN + q) * 32;
        #pragma unroll
        for (int c = 0; c < 32; c++) s_fc[tid][4 + c]  = focal_fc(p2[c]);
        const float* p3 = l3 + ((size_t)b * QN + q) * 8;
        #pragma unroll
        for (int c = 0; c < 8; c++)  s_fc[tid][36 + c] = focal_fc(p3[c]);
    }
    __syncthreads();
    if (!qv) return;

    const float* pq = pbx + ((size_t)b * QN + q) * 4;
    float px0 = pq[0], py0 = pq[1], px1 = pq[2], py1 = pq[3];
    float ax = (px0 + px1) * 0.5f, ay = (py0 + py1) * 0.5f;
    float areaA = (px1 - px0) * (py1 - py0);
    float np0 = px0 / s_isz[0], np1 = py0 / s_isz[1];
    float np2 = px1 / s_isz[2], np3 = py1 / s_isz[3];

    bool fg = false;
    for (int g = 0; g < GN; g++) {
        bool ib = (ax > s_bb[g][0]) && (ax < s_bb[g][2]) && (ay > s_bb[g][1]) && (ay < s_bb[g][3]);
        bool ic = (ax > s_cb[g][0]) && (ax < s_cb[g][1]) && (ay > s_cb[g][2]) && (ay < s_cb[g][3]);
        fg = fg || ib || ic;
    }
    float fgpen = fg ? 0.0f : 10000.0f;

    float* orow = costOut + ((size_t)b * QN + q) * GN;
    float* tcol = &g_costT[b][0][q];
    float tmp0 = 0, tmp1 = 0, tmp2 = 0;
    for (int g = 0; g < GN; g++) {
        bool ib = (ax > s_bb[g][0]) && (ax < s_bb[g][2]) && (ay > s_bb[g][1]) && (ay < s_bb[g][3]);
        bool ic = (ax > s_cb[g][0]) && (ax < s_cb[g][1]) && (ay > s_cb[g][2]) && (ay < s_cb[g][3]);
        float cc = s_fc[tid][s_t1[g]] + s_fc[tid][4 + s_t2[g]] + s_fc[tid][36 + s_t3[g]];
        float cb = fabsf(np0 - s_ng[g][0]) + fabsf(np1 - s_ng[g][1]) +
                   fabsf(np2 - s_ng[g][2]) + fabsf(np3 - s_ng[g][3]);
        float gx0 = s_g[g][0], gy0 = s_g[g][1], gx1 = s_g[g][2], gy1 = s_g[g][3];
        float iw = fmaxf(fminf(px1, gx1) - fmaxf(px0, gx0), 0.0f);
        float ih = fmaxf(fminf(py1, gy1) - fmaxf(py0, gy0), 0.0f);
        float inter = iw * ih;
        float uni = areaA + s_ab[g] - inter;
        float iou = inter / uni;
        float cw = fmaxf(fmaxf(px1, gx1) - fminf(px0, gx0), 0.0f);
        float ch = fmaxf(fmaxf(py1, gy1) - fminf(py0, gy0), 0.0f);
        float carea = cw * ch;
        float giou = iou - (carea - uni) / carea;
        float cost = cb + 0.33333334f * cc + (-giou) + ((ib && ic) ? 0.0f : 100.0f) + fgpen;
        tcol[(size_t)g * QN] = cost;   // coalesced across threads (consecutive q)
        int lg = g & 3;
        if      (lg == 0) tmp0 = cost;
        else if (lg == 1) tmp1 = cost;
        else if (lg == 2) tmp2 = cost;
        else ((float4*)orow)[g >> 2] = make_float4(tmp0, tmp1, tmp2, cost);
    }
}

// ---------------------------------------------------------------------------
// Kernel 2: per-(b,g) top-5 (one warp per gt column) -> g_dk, g_pos
// ---------------------------------------------------------------------------
__global__ void __launch_bounds__(256)
topk_kernel(const float* __restrict__ pbx,
            const float* __restrict__ gbx)
{
    const int wg   = blockIdx.x * 8 + (threadIdx.x >> 5);
    const int lane = threadIdx.x & 31;
    if (wg >= BN * GN) return;
    const int b = wg / GN, g = wg % GN;

    const float* col = g_costT[b][g];
    const float* g4 = gbx + ((size_t)b * GN + g) * 4;
    float gx0 = g4[0], gy0 = g4[1], gx1 = g4[2], gy1 = g4[3];
    float areaB = (gx1 - gx0) * (gy1 - gy0);

    float iv0 = -INFINITY, iv1 = -INFINITY, iv2 = -INFINITY, iv3 = -INFINITY, iv4 = -INFINITY;
    float cv0 = INFINITY, cv1 = INFINITY, cv2 = INFINITY, cv3 = INFINITY, cv4 = INFINITY;
    int   ci0 = 0x7fffffff, ci1 = 0x7fffffff, ci2 = 0x7fffffff, ci3 = 0x7fffffff, ci4 = 0x7fffffff;

    for (int q = lane; q < QN; q += 32) {
        float4 p = ((const float4*)pbx)[(size_t)b * QN + q];
        float areaA = (p.z - p.x) * (p.w - p.y);
        float iw = fmaxf(fminf(p.z, gx1) - fmaxf(p.x, gx0), 0.0f);
        float ih = fmaxf(fminf(p.w, gy1) - fmaxf(p.y, gy0), 0.0f);
        float inter = iw * ih;
        float iou = inter / (areaA + areaB - inter);
        if (iou > iv4) {
            if      (iou > iv0) { iv4=iv3; iv3=iv2; iv2=iv1; iv1=iv0; iv0=iou; }
            else if (iou > iv1) { iv4=iv3; iv3=iv2; iv2=iv1; iv1=iou; }
            else if (iou > iv2) { iv4=iv3; iv3=iv2; iv2=iou; }
            else if (iou > iv3) { iv4=iv3; iv3=iou; }
            else                { iv4=iou; }
        }
        float c = col[q];
        if (c < cv4) {
            if      (c < cv0) { cv4=cv3;ci4=ci3; cv3=cv2;ci3=ci2; cv2=cv1;ci2=ci1; cv1=cv0;ci1=ci0; cv0=c;ci0=q; }
            else if (c < cv1) { cv4=cv3;ci4=ci3; cv3=cv2;ci3=ci2; cv2=cv1;ci2=ci1; cv1=c;ci1=q; }
            else if (c < cv2) { cv4=cv3;ci4=ci3; cv3=cv2;ci3=ci2; cv2=c;ci2=q; }
            else if (c < cv3) { cv4=cv3;ci4=ci3; cv3=c;ci3=q; }
            else              { cv4=c;ci4=q; }
        }
    }
    // iou top-5 merge (descending pop order)
    float s = 0.0f;
    for (int r = 0; r < 5; r++) {
        float mv = iv0;
        for (int off = 16; off; off >>= 1)
            mv = fmaxf(mv, __shfl_xor_sync(0xffffffffu, mv, off));
        s += mv;
        unsigned ball = __ballot_sync(0xffffffffu, iv0 == mv);
        if (lane == (__ffs(ball) - 1)) { iv0=iv1; iv1=iv2; iv2=iv3; iv3=iv4; iv4=-INFINITY; }
    }
    if (lane == 0) { int d = (int)s; if (d < 1) d = 1; if (d > 5) d = 5; g_dk[b][g] = d; }
    // cost top-5 merge (stable smaller-index-first)
    for (int r = 0; r < 5; r++) {
        float mv = cv0; int mi = ci0;
        for (int off = 16; off; off >>= 1) {
            float ov = __shfl_xor_sync(0xffffffffu, mv, off);
            int   oi = __shfl_xor_sync(0xffffffffu, mi, off);
            if (ov < mv || (ov == mv && oi < mi)) { mv = ov; mi = oi; }
        }
        if (lane == 0) g_pos[b][g * 5 + r] = mi;
        if (cv0 == mv && ci0 == mi) {
            cv0=cv1;ci0=ci1; cv1=cv2;ci1=ci2; cv2=cv3;ci2=ci3; cv3=cv4;ci3=ci4;
            cv4=INFINITY; ci4=0x7fffffff;
        }
    }
}

// ---------------------------------------------------------------------------
// Kernel 3: per-image sequential matching core (writes g_rowbits / g_addc)
// ---------------------------------------------------------------------------
__device__ __forceinline__ void resolve_rows(unsigned* rowbits,
                                             unsigned short* addc,
                                             const float* __restrict__ costB,
                                             int tid)
{
    for (int q = tid; q < QN; q += TPB) {
        unsigned a0 = rowbits[q * 4 + 0], a1 = rowbits[q * 4 + 1];
        unsigned a2 = rowbits[q * 4 + 2], a3 = rowbits[q * 4 + 3];
        int pc = __popc(a0) + __popc(a1) + __popc(a2) + __popc(a3);
        if (pc > 1) {
            const float* cr = costB + (size_t)q * GN;
            int a = addc[q];
            float best = INFINITY; int bg = 0;
            for (int g = 0; g < GN; g++) {
                float v = apply_adds(cr[g], a);
                if (v < best) { best = v; bg = g; }
            }
            rowbits[q * 4 + 0] = 0; rowbits[q * 4 + 1] = 0;
            rowbits[q * 4 + 2] = 0; rowbits[q * 4 + 3] = 0;
            rowbits[q * 4 + (bg >> 5)] = 1u << (bg & 31);
        }
    }
}

__global__ void __launch_bounds__(TPB)
match_core(const float* __restrict__ costG)
{
    const int b    = blockIdx.x;
    const int tid  = threadIdx.x;
    const int lane = tid & 31;
    const int w    = tid >> 5;

    extern __shared__ unsigned char smemraw[];
    unsigned*       rowbits = (unsigned*)smemraw;
    unsigned short* addc    = (unsigned short*)(rowbits + QN * 4);
    int*   colc = (int*)(addc + QN);
    int*   unm  = colc + GN;
    int*   ctrl = unm + GN;

    const float* costB = costG + (size_t)b * QN * GN;

    for (int i = tid; i < QN * 4; i += TPB) rowbits[i] = 0;
    for (int q = tid; q < QN; q += TPB) addc[q] = 0;
    __syncthreads();
    if (tid < GN) {
        int d = g_dk[b][tid];
        unsigned bit = 1u << (tid & 31);
        int word = tid >> 5;
        for (int j = 0; j < d; j++)
            atomicOr(&rowbits[g_pos[b][tid * 5 + j] * 4 + word], bit);
    }
    __syncthreads();

    resolve_rows(rowbits, addc, costB, tid);
    __syncthreads();

    for (int iter = 0; iter < 100000; iter++) {
        if (tid < GN) colc[tid] = 0;
        if (tid == 0) ctrl[0] = 0;
        __syncthreads();
        for (int q = tid; q < QN; q += TPB) {
            #pragma unroll
            for (int ww = 0; ww < 4; ww++) {
                unsigned bits = rowbits[q * 4 + ww];
                while (bits) {
                    int g = ww * 32 + __ffs(bits) - 1;
                    bits &= bits - 1;
                    atomicAdd(&colc[g], 1);
                }
            }
        }
        __syncthreads();
        if (tid < GN && colc[tid] == 0) { int p = atomicAdd(&ctrl[0], 1); unm[p] = tid; }
        __syncthreads();
        int nu = ctrl[0];
        if (nu == 0) break;

        // (a) penalty: rows currently assigned get +1e5 (tracked as a count)
        for (int q = tid; q < QN; q += TPB) {
            unsigned a0 = rowbits[q*4], a1 = rowbits[q*4+1], a2 = rowbits[q*4+2], a3 = rowbits[q*4+3];
            if (a0 | a1 | a2 | a3) addc[q]++;
        }
        __syncthreads();

        // (b) fill all unmatched columns in parallel — one warp per column.
        //     All columns use the same addc state (matches reference body).
        //     Unmatched columns have no existing bits, so atomicOr == one-hot set.
        for (int k = w; k < nu; k += TPB / 32) {
            int g = unm[k];
            const float* col = g_costT[b][g];
            float bv = INFINITY; int bi = 0x7fffffff;
            for (int q = lane; q < QN; q += 32) {
                float v = apply_adds(col[q], addc[q]);
                if (v < bv || (v == bv && q < bi)) { bv = v; bi = q; }
            }
            for (int off = 16; off; off >>= 1) {
                float ov = __shfl_xor_sync(0xffffffffu, bv, off);
                int   oi = __shfl_xor_sync(0xffffffffu, bi, off);
                if (ov < bv || (ov == bv && oi < bi)) { bv = ov; bi = oi; }
            }
            if (lane == 0)
                atomicOr(&rowbits[bi * 4 + (g >> 5)], 1u << (g & 31));
        }
        __syncthreads();

        // (c) resolve with updated c
        resolve_rows(rowbits, addc, costB, tid);
        __syncthreads();
    }
    __syncthreads();

    // dump state to global scratch for the full-grid finishers
    for (int i = tid; i < QN * 4; i += TPB) g_rowbits[b][i] = rowbits[i];
    for (int q = tid; q < QN; q += TPB)    g_addc[b][q]    = addc[q];
}

// ---------------------------------------------------------------------------
// Kernel 4: full-grid expansion of m / selected / gt_idx
// ---------------------------------------------------------------------------
__global__ void __launch_bounds__(256)
expand_kernel(float* __restrict__ out_m,
              float* __restrict__ out_sel,
              float* __restrict__ out_gti)
{
    const int nth = gridDim.x * 256;
    const int t0  = blockIdx.x * 256 + threadIdx.x;

    const int NM = BN * QN * (GN / 4);
    for (int t = t0; t < NM; t += nth) {
        int bq = t / (GN / 4);
        int c4 = t - bq * (GN / 4);
        int b  = bq / QN;
        int q  = bq - b * QN;
        int g0 = c4 * 4;
        unsigned wbits = g_rowbits[b][q * 4 + (g0 >> 5)] >> (g0 & 31);
        float4 v;
        v.x = (wbits & 1u) ? 1.0f : 0.0f;
        v.y = ((wbits >> 1) & 1u) ? 1.0f : 0.0f;
        v.z = ((wbits >> 2) & 1u) ? 1.0f : 0.0f;
        v.w = ((wbits >> 3) & 1u) ? 1.0f : 0.0f;
        ((float4*)out_m)[t] = v;
    }

    const int NS = BN * QN;
    for (int t = t0; t < NS; t += nth) {
        int b = t / QN, q = t - b * QN;
        unsigned a0 = g_rowbits[b][q*4], a1 = g_rowbits[b][q*4+1];
        unsigned a2 = g_rowbits[b][q*4+2], a3 = g_rowbits[b][q*4+3];
        bool sel = (a0 | a1 | a2 | a3) != 0;
        int g = 0;
        if      (a0) g = __ffs(a0) - 1;
        else if (a1) g = 32 + __ffs(a1) - 1;
        else if (a2) g = 64 + __ffs(a2) - 1;
        else if (a3) g = 96 + __ffs(a3) - 1;
        out_sel[t] = sel ? 1.0f : 0.0f;
        out_gti[t] = (float)g;
    }
}

// ---------------------------------------------------------------------------
// Kernel 5: matched_qidx — one warp per (b,g), coalesced column reads
// ---------------------------------------------------------------------------
__global__ void __launch_bounds__(256)
mq_kernel(float* __restrict__ out_mq)
{
    const int wg   = blockIdx.x * 8 + (threadIdx.x >> 5);
    const int lane = threadIdx.x & 31;
    if (wg >= BN * GN) return;
    const int b = wg / GN, g = wg % GN;
    const float* col = g_costT[b][g];
    const unsigned* rb = g_rowbits[b];

    float bv = INFINITY; int bi = 0x7fffffff;
    for (int q = lane; q < QN; q += 32) {
        if ((rb[q * 4 + (g >> 5)] >> (g & 31)) & 1u) {
            float v = apply_adds(col[q], g_addc[b][q]);
            if (v < bv || (v == bv && q < bi)) { bv = v; bi = q; }
        }
    }
    for (int off = 16; off; off >>= 1) {
        float ov = __shfl_xor_sync(0xffffffffu, bv, off);
        int   oi = __shfl_xor_sync(0xffffffffu, bi, off);
        if (ov < bv || (ov == bv && oi < bi)) { bv = ov; bi = oi; }
    }
    if (lane == 0)
        out_mq[(size_t)b * GN + g] = (bi == 0x7fffffff) ? 0.0f : (float)bi;
}

// ---------------------------------------------------------------------------
extern "C" void kernel_launch(void* const* d_in, const int* in_sizes, int n_in,
                              void* d_out, int out_size)
{
    const float* l1  = (const float*)d_in[0];
    const float* l2  = (const float*)d_in[1];
    const float* l3  = (const float*)d_in[2];
    const float* pb  = (const float*)d_in[3];
    const float* gb  = (const float*)d_in[4];
    const float* isz = (const float*)d_in[5];
    const int*   t1  = (const int*)d_in[6];
    const int*   t2  = (const int*)d_in[7];
    const int*   t3  = (const int*)d_in[8];

    float* out = (float*)d_out;
    float* o_m    = out;
    float* o_sel  = o_m   + (size_t)BN * QN * GN;
    float* o_gti  = o_sel + (size_t)BN * QN;
    float* o_mq   = o_gti + (size_t)BN * QN;
    float* o_cost = o_mq  + (size_t)BN * GN;

    dim3 grid1((QN + 127) / 128, BN);
    cost_kernel<<<grid1, 128>>>(l1, l2, l3, pb, gb, isz, t1, t2, t3, o_cost);

    topk_kernel<<<(BN * GN + 7) / 8, 256>>>(pb, gb);

    const int smem = QN * 4 * 4 + QN * 2 + (GN + GN) * 4 + 16;
    cudaFuncSetAttribute(match_core, cudaFuncAttributeMaxDynamicSharedMemorySize, smem);
    match_core<<<BN, TPB, smem>>>(o_cost);

    expand_kernel<<<2048, 256>>>(o_m, o_sel, o_gti);
    mq_kernel<<<(BN * GN + 7) / 8, 256>>>(o_mq);
}

// round 16
// speedup vs baseline: 1.1033x; 1.1033x over previous
#include <cuda_runtime.h>
#include <math.h>

#define QN 4000
#define GN 100
#define BN 32
#define TPB 1024

// ---------------- device scratch (no allocs allowed) ----------------
__device__ unsigned       g_rowbits[BN][QN * 4];
__device__ unsigned short g_addc[BN][QN];
__device__ int            g_dk[BN][GN];
__device__ int            g_pos[BN][GN * 5];
__device__ float          g_costT[BN][GN][QN];   // transposed cost (column-major)

// ---------------------------------------------------------------------------
__device__ __forceinline__ float focal_fc(float x) {
    float p = 1.0f / (1.0f + expf(-x));
    float pos = 0.25f * (1.0f - p) * (1.0f - p) * (-logf(p + 1e-8f));
    float neg = 0.75f * p * p * (-logf(1.0f - p + 1e-8f));
    return pos - neg;
}

// reference's iterative "+100000.0" with per-step float rounding (mq only)
__device__ __forceinline__ float apply_adds(float v, int a) {
    for (int i = 0; i < a; i++) v += 100000.0f;
    return v;
}

// ---------------------------------------------------------------------------
// Kernel 1: cost[B,Q,G] row-major into output + transposed copy into g_costT
// ---------------------------------------------------------------------------
__global__ void cost_kernel(const float* __restrict__ l1,
                            const float* __restrict__ l2,
                            const float* __restrict__ l3,
                            const float* __restrict__ pbx,
                            const float* __restrict__ gbx,
                            const float* __restrict__ iszg,
                            const int*  __restrict__ t1,
                            const int*  __restrict__ t2,
                            const int*  __restrict__ t3,
                            float* __restrict__ costOut)
{
    const int b   = blockIdx.y;
    const int tid = threadIdx.x;
    const int q   = blockIdx.x * 128 + tid;

    __shared__ float s_g[GN][4];
    __shared__ float s_bb[GN][4];
    __shared__ float s_cb[GN][4];
    __shared__ float s_ng[GN][4];
    __shared__ float s_ab[GN];
    __shared__ int   s_t1[GN], s_t2[GN], s_t3[GN];
    __shared__ float s_isz[4];
    __shared__ float s_fc[128][45];

    if (tid < GN) {
        const float* g4 = gbx + ((size_t)b * GN + tid) * 4;
        float gx0 = g4[0], gy0 = g4[1], gx1 = g4[2], gy1 = g4[3];
        s_g[tid][0] = gx0; s_g[tid][1] = gy0; s_g[tid][2] = gx1; s_g[tid][3] = gy1;
        float gcx = (gx0 + gx1) * 0.5f, gcy = (gy0 + gy1) * 0.5f;
        float gw = gx1 - gx0, gh = gy1 - gy0;
        float bx0 = gcx - 0.5f * gw, by0 = gcy - 0.5f * gh;
        float bx1 = gcx + 0.5f * gw, by1 = gcy + 0.5f * gh;
        s_bb[tid][0] = bx0; s_bb[tid][1] = by0; s_bb[tid][2] = bx1; s_bb[tid][3] = by1;
        float w2 = bx1 - bx0, h2 = by1 - by0;
        s_cb[tid][0] = gcx - 2.5f * w2; s_cb[tid][1] = gcx + 2.5f * w2;
        s_cb[tid][2] = gcy - 2.5f * h2; s_cb[tid][3] = gcy + 2.5f * h2;
        s_ab[tid] = (gx1 - gx0) * (gy1 - gy0);
        const float* is = iszg + (size_t)b * 4;
        s_ng[tid][0] = gx0 / is[0]; s_ng[tid][1] = gy0 / is[1];
        s_ng[tid][2] = gx1 / is[2]; s_ng[tid][3] = gy1 / is[3];
        s_t1[tid] = t1[b * GN + tid];
        s_t2[tid] = t2[b * GN + tid];
        s_t3[tid] = t3[b * GN + tid];
    }
    if (tid < 4) s_isz[tid] = iszg[(size_t)b * 4 + tid];

    const bool qv = (q < QN);
    if (qv) {
        const float* p1 = l1 + ((size_t)b * QN + q) * 4;
        #pragma unroll
        for (int c = 0; c < 4; c++)  s_fc[tid][c]      = focal_fc(p1[c]);
        const float* p2 = l2 + ((size_t)b * QN + q) * 32;
        #pragma unroll
        for (int c = 0; c < 32; c++) s_fc[tid][4 + c]  = focal_fc(p2[c]);
        const float* p3 = l3 + ((size_t)b * QN + q) * 8;
        #pragma unroll
        for (int c = 0; c < 8; c++)  s_fc[tid][36 + c] = focal_fc(p3[c]);
    }
    __syncthreads();
    if (!qv) return;

    const float* pq = pbx + ((size_t)b * QN + q) * 4;
    float px0 = pq[0], py0 = pq[1], px1 = pq[2], py1 = pq[3];
    float ax = (px0 + px1) * 0.5f, ay = (py0 + py1) * 0.5f;
    float areaA = (px1 - px0) * (py1 - py0);
    float np0 = px0 / s_isz[0], np1 = py0 / s_isz[1];
    float np2 = px1 / s_isz[2], np3 = py1 / s_isz[3];

    bool fg = false;
    for (int g = 0; g < GN; g++) {
        bool ib = (ax > s_bb[g][0]) && (ax < s_bb[g][2]) && (ay > s_bb[g][1]) && (ay < s_bb[g][3]);
        bool ic = (ax > s_cb[g][0]) && (ax < s_cb[g][1]) && (ay > s_cb[g][2]) && (ay < s_cb[g][3]);
        fg = fg || ib || ic;
    }
    float fgpen = fg ? 0.0f : 10000.0f;

    float* orow = costOut + ((size_t)b * QN + q) * GN;
    float* tcol = &g_costT[b][0][q];
    float tmp0 = 0, tmp1 = 0, tmp2 = 0;
    for (int g = 0; g < GN; g++) {
        bool ib = (ax > s_bb[g][0]) && (ax < s_bb[g][2]) && (ay > s_bb[g][1]) && (ay < s_bb[g][3]);
        bool ic = (ax > s_cb[g][0]) && (ax < s_cb[g][1]) && (ay > s_cb[g][2]) && (ay < s_cb[g][3]);
        float cc = s_fc[tid][s_t1[g]] + s_fc[tid][4 + s_t2[g]] + s_fc[tid][36 + s_t3[g]];
        float cb = fabsf(np0 - s_ng[g][0]) + fabsf(np1 - s_ng[g][1]) +
                   fabsf(np2 - s_ng[g][2]) + fabsf(np3 - s_ng[g][3]);
        float gx0 = s_g[g][0], gy0 = s_g[g][1], gx1 = s_g[g][2], gy1 = s_g[g][3];
        float iw = fmaxf(fminf(px1, gx1) - fmaxf(px0, gx0), 0.0f);
        float ih = fmaxf(fminf(py1, gy1) - fmaxf(py0, gy0), 0.0f);
        float inter = iw * ih;
        float uni = areaA + s_ab[g] - inter;
        float iou = inter / uni;
        float cw = fmaxf(fmaxf(px1, gx1) - fminf(px0, gx0), 0.0f);
        float ch = fmaxf(fmaxf(py1, gy1) - fminf(py0, gy0), 0.0f);
        float carea = cw * ch;
        float giou = iou - (carea - uni) / carea;
        float cost = cb + 0.33333334f * cc + (-giou) + ((ib && ic) ? 0.0f : 100.0f) + fgpen;
        tcol[(size_t)g * QN] = cost;   // coalesced across threads (consecutive q)
        int lg = g & 3;
        if      (lg == 0) tmp0 = cost;
        else if (lg == 1) tmp1 = cost;
        else if (lg == 2) tmp2 = cost;
        else ((float4*)orow)[g >> 2] = make_float4(tmp0, tmp1, tmp2, cost);
    }
}

// ---------------------------------------------------------------------------
// Kernel 2: per-(b,g) top-5 (one warp per gt column) -> g_dk, g_pos
// ---------------------------------------------------------------------------
__global__ void __launch_bounds__(256)
topk_kernel(const float* __restrict__ pbx,
            const float* __restrict__ gbx)
{
    const int wg   = blockIdx.x * 8 + (threadIdx.x >> 5);
    const int lane = threadIdx.x & 31;
    if (wg >= BN * GN) return;
    const int b = wg / GN, g = wg % GN;

    const float* col = g_costT[b][g];
    const float* g4 = gbx + ((size_t)b * GN + g) * 4;
    float gx0 = g4[0], gy0 = g4[1], gx1 = g4[2], gy1 = g4[3];
    float areaB = (gx1 - gx0) * (gy1 - gy0);

    float iv0 = -INFINITY, iv1 = -INFINITY, iv2 = -INFINITY, iv3 = -INFINITY, iv4 = -INFINITY;
    float cv0 = INFINITY, cv1 = INFINITY, cv2 = INFINITY, cv3 = INFINITY, cv4 = INFINITY;
    int   ci0 = 0x7fffffff, ci1 = 0x7fffffff, ci2 = 0x7fffffff, ci3 = 0x7fffffff, ci4 = 0x7fffffff;

    for (int q = lane; q < QN; q += 32) {
        float4 p = ((const float4*)pbx)[(size_t)b * QN + q];
        float areaA = (p.z - p.x) * (p.w - p.y);
        float iw = fmaxf(fminf(p.z, gx1) - fmaxf(p.x, gx0), 0.0f);
        float ih = fmaxf(fminf(p.w, gy1) - fmaxf(p.y, gy0), 0.0f);
        float inter = iw * ih;
        float iou = inter / (areaA + areaB - inter);
        if (iou > iv4) {
            if      (iou > iv0) { iv4=iv3; iv3=iv2; iv2=iv1; iv1=iv0; iv0=iou; }
            else if (iou > iv1) { iv4=iv3; iv3=iv2; iv2=iv1; iv1=iou; }
            else if (iou > iv2) { iv4=iv3; iv3=iv2; iv2=iou; }
            else if (iou > iv3) { iv4=iv3; iv3=iou; }
            else                { iv4=iou; }
        }
        float c = col[q];
        if (c < cv4) {
            if      (c < cv0) { cv4=cv3;ci4=ci3; cv3=cv2;ci3=ci2; cv2=cv1;ci2=ci1; cv1=cv0;ci1=ci0; cv0=c;ci0=q; }
            else if (c < cv1) { cv4=cv3;ci4=ci3; cv3=cv2;ci3=ci2; cv2=cv1;ci2=ci1; cv1=c;ci1=q; }
            else if (c < cv2) { cv4=cv3;ci4=ci3; cv3=cv2;ci3=ci2; cv2=c;ci2=q; }
            else if (c < cv3) { cv4=cv3;ci4=ci3; cv3=c;ci3=q; }
            else              { cv4=c;ci4=q; }
        }
    }
    // iou top-5 merge (descending pop order)
    float s = 0.0f;
    for (int r = 0; r < 5; r++) {
        float mv = iv0;
        for (int off = 16; off; off >>= 1)
            mv = fmaxf(mv, __shfl_xor_sync(0xffffffffu, mv, off));
        s += mv;
        unsigned ball = __ballot_sync(0xffffffffu, iv0 == mv);
        if (lane == (__ffs(ball) - 1)) { iv0=iv1; iv1=iv2; iv2=iv3; iv3=iv4; iv4=-INFINITY; }
    }
    if (lane == 0) { int d = (int)s; if (d < 1) d = 1; if (d > 5) d = 5; g_dk[b][g] = d; }
    // cost top-5 merge (stable smaller-index-first)
    for (int r = 0; r < 5; r++) {
        float mv = cv0; int mi = ci0;
        for (int off = 16; off; off >>= 1) {
            float ov = __shfl_xor_sync(0xffffffffu, mv, off);
            int   oi = __shfl_xor_sync(0xffffffffu, mi, off);
            if (ov < mv || (ov == mv && oi < mi)) { mv = ov; mi = oi; }
        }
        if (lane == 0) g_pos[b][g * 5 + r] = mi;
        if (cv0 == mv && ci0 == mi) {
            cv0=cv1;ci0=ci1; cv1=cv2;ci1=ci2; cv2=cv3;ci2=ci3; cv3=cv4;ci3=ci4;
            cv4=INFINITY; ci4=0x7fffffff;
        }
    }
}

// ---------------------------------------------------------------------------
// Kernel 3: per-image matching core with incremental state.
// Invariants used (provable from the reference semantics):
//  * assigned-row set grows monotonically; addc[q] = E - stamp[q]
//  * fill argmin is always among unassigned rows, comparing RAW cost
//    (penalized >= ~99999 > max raw ~10107, and unassigned rows always exist)
//  * conflicted rows are always first-assigned this iteration -> penalty 0
//    -> resolve full-row argmin uses RAW cost
// ---------------------------------------------------------------------------
__global__ void __launch_bounds__(TPB)
match_core(const float* __restrict__ costG)
{
    const int b    = blockIdx.x;
    const int tid  = threadIdx.x;
    const int lane = tid & 31;
    const int w    = tid >> 5;

    extern __shared__ unsigned char smemraw[];
    unsigned*       rowbits = (unsigned*)smemraw;                  // QN*4 = 64000B
    unsigned short* stamp   = (unsigned short*)(rowbits + QN * 4); // QN   =  8000B
    int* fillcnt = (int*)(stamp + QN);                             // QN   = 16000B
    int* colc    = fillcnt + QN;                                   // GN
    int* unm     = colc + GN;                                      // GN
    int* flist   = unm + GN;                                       // 128
    int* conf    = flist + 128;                                    // 512
    int* cnt     = conf + 512;                                     // 4

    const float* costB = costG + (size_t)b * QN * GN;

    for (int i = tid; i < QN * 4; i += TPB) rowbits[i] = 0;
    for (int q = tid; q < QN; q += TPB) { stamp[q] = 0xFFFF; fillcnt[q] = 0; }
    __syncthreads();
    if (tid < GN) {
        int d = g_dk[b][tid];
        unsigned bit = 1u << (tid & 31);
        int word = tid >> 5;
        for (int j = 0; j < d; j++)
            atomicOr(&rowbits[g_pos[b][tid * 5 + j] * 4 + word], bit);
    }
    if (tid == 0) cnt[2] = 0;
    __syncthreads();

    // mark initial stamps, collect initial multi-rows
    for (int q = tid; q < QN; q += TPB) {
        unsigned a0 = rowbits[q*4], a1 = rowbits[q*4+1], a2 = rowbits[q*4+2], a3 = rowbits[q*4+3];
        if (a0 | a1 | a2 | a3) {
            stamp[q] = 0;
            if (__popc(a0) + __popc(a1) + __popc(a2) + __popc(a3) > 1)
                conf[atomicAdd(&cnt[2], 1)] = q;
        }
    }
    __syncthreads();

    // initial resolve: warp per conflicted row, full-row raw argmin
    int ncf = cnt[2];
    for (int i = w; i < ncf; i += TPB / 32) {
        int q = conf[i];
        const float* cr = costB + (size_t)q * GN;
        float bv = INFINITY; int bg = 0x7fffffff;
        for (int g = lane; g < GN; g += 32) {
            float v = cr[g];
            if (v < bv || (v == bv && g < bg)) { bv = v; bg = g; }
        }
        for (int off = 16; off; off >>= 1) {
            float ov = __shfl_xor_sync(0xffffffffu, bv, off);
            int   og = __shfl_xor_sync(0xffffffffu, bg, off);
            if (ov < bv || (ov == bv && og < bg)) { bv = ov; bg = og; }
        }
        if (lane == 0) {
            rowbits[q*4] = 0; rowbits[q*4+1] = 0; rowbits[q*4+2] = 0; rowbits[q*4+3] = 0;
            rowbits[q*4 + (bg >> 5)] = 1u << (bg & 31);
        }
    }
    __syncthreads();

    // build colc once
    if (tid < GN) colc[tid] = 0;
    __syncthreads();
    for (int q = tid; q < QN; q += TPB) {
        #pragma unroll
        for (int ww = 0; ww < 4; ww++) {
            unsigned bits = rowbits[q * 4 + ww];
            while (bits) { int g = ww * 32 + __ffs(bits) - 1; bits &= bits - 1; atomicAdd(&colc[g], 1); }
        }
    }
    __syncthreads();

    int E = 0;
    for (int e = 1; e <= 100000; e++) {
        if (tid == 0) { cnt[0] = 0; cnt[1] = 0; cnt[2] = 0; }
        __syncthreads();
        if (tid < GN && colc[tid] == 0) unm[atomicAdd(&cnt[0], 1)] = tid;
        __syncthreads();
        int nu = cnt[0];
        if (nu == 0) break;
        E = e;

        // fill: one warp per unmatched column, raw cost over unassigned rows
        for (int k = w; k < nu; k += TPB / 32) {
            int g = unm[k];
            const float* col = g_costT[b][g];
            float bv = INFINITY; int bi = 0x7fffffff;
            for (int q = lane; q < QN; q += 32) {
                float v = col[q];
                if (stamp[q] == 0xFFFF && (v < bv || (v == bv && q < bi))) { bv = v; bi = q; }
            }
            for (int off = 16; off; off >>= 1) {
                float ov = __shfl_xor_sync(0xffffffffu, bv, off);
                int   oi = __shfl_xor_sync(0xffffffffu, bi, off);
                if (ov < bv || (ov == bv && oi < bi)) { bv = ov; bi = oi; }
            }
            if (lane == 0) {
                int old = atomicAdd(&fillcnt[bi], 1);
                atomicOr(&rowbits[bi * 4 + (g >> 5)], 1u << (g & 31));
                colc[g] = 1;
                if (old == 0)      flist[atomicAdd(&cnt[1], 1)] = bi;
                else if (old == 1) conf[atomicAdd(&cnt[2], 1)] = bi;
            }
        }
        __syncthreads();

        // resolve conflicts (few): warp per row, full-row raw argmin, incremental colc
        ncf = cnt[2];
        for (int i = w; i < ncf; i += TPB / 32) {
            int q = conf[i];
            const float* cr = costB + (size_t)q * GN;
            float bv = INFINITY; int bg = 0x7fffffff;
            for (int g = lane; g < GN; g += 32) {
                float v = cr[g];
                if (v < bv || (v == bv && g < bg)) { bv = v; bg = g; }
            }
            for (int off = 16; off; off >>= 1) {
                float ov = __shfl_xor_sync(0xffffffffu, bv, off);
                int   og = __shfl_xor_sync(0xffffffffu, bg, off);
                if (ov < bv || (ov == bv && og < bg)) { bv = ov; bg = og; }
            }
            if (lane == 0) {
                bool had = false;
                #pragma unroll
                for (int ww = 0; ww < 4; ww++) {
                    unsigned bits = rowbits[q * 4 + ww];
                    unsigned keep = (ww == (bg >> 5)) ? (1u << (bg & 31)) : 0u;
                    if (bits & keep) had = true;
                    unsigned rm = bits & ~keep;
                    while (rm) { int gg = ww * 32 + __ffs(rm) - 1; rm &= rm - 1; atomicSub(&colc[gg], 1); }
                    rowbits[q * 4 + ww] = keep;
                }
                if (!had) atomicAdd(&colc[bg], 1);
            }
        }
        __syncthreads();

        // stamps + reset fill counters (touched rows only)
        int nf = cnt[1];
        for (int i = tid; i < nf; i += TPB) {
            int q = flist[i];
            stamp[q] = (unsigned short)e;
            fillcnt[q] = 0;
        }
        __syncthreads();
    }

    // dump state for the full-grid finishers
    for (int i = tid; i < QN * 4; i += TPB) g_rowbits[b][i] = rowbits[i];
    for (int q = tid; q < QN; q += TPB) {
        unsigned short s = stamp[q];
        g_addc[b][q] = (s == 0xFFFF) ? 0 : (unsigned short)(E - s);
    }
}

// ---------------------------------------------------------------------------
// Kernel 4: full-grid expansion of m / selected / gt_idx
// ---------------------------------------------------------------------------
__global__ void __launch_bounds__(256)
expand_kernel(float* __restrict__ out_m,
              float* __restrict__ out_sel,
              float* __restrict__ out_gti)
{
    const int nth = gridDim.x * 256;
    const int t0  = blockIdx.x * 256 + threadIdx.x;

    const int NM = BN * QN * (GN / 4);
    for (int t = t0; t < NM; t += nth) {
        int bq = t / (GN / 4);
        int c4 = t - bq * (GN / 4);
        int b  = bq / QN;
        int q  = bq - b * QN;
        int g0 = c4 * 4;
        unsigned wbits = g_rowbits[b][q * 4 + (g0 >> 5)] >> (g0 & 31);
        float4 v;
        v.x = (wbits & 1u) ? 1.0f : 0.0f;
        v.y = ((wbits >> 1) & 1u) ? 1.0f : 0.0f;
        v.z = ((wbits >> 2) & 1u) ? 1.0f : 0.0f;
        v.w = ((wbits >> 3) & 1u) ? 1.0f : 0.0f;
        ((float4*)out_m)[t] = v;
    }

    const int NS = BN * QN;
    for (int t = t0; t < NS; t += nth) {
        int b = t / QN, q = t - b * QN;
        unsigned a0 = g_rowbits[b][q*4], a1 = g_rowbits[b][q*4+1];
        unsigned a2 = g_rowbits[b][q*4+2], a3 = g_rowbits[b][q*4+3];
        bool sel = (a0 | a1 | a2 | a3) != 0;
        int g = 0;
        if      (a0) g = __ffs(a0) - 1;
        else if (a1) g = 32 + __ffs(a1) - 1;
        else if (a2) g = 64 + __ffs(a2) - 1;
        else if (a3) g = 96 + __ffs(a3) - 1;
        out_sel[t] = sel ? 1.0f : 0.0f;
        out_gti[t] = (float)g;
    }
}

// ---------------------------------------------------------------------------
// Kernel 5: matched_qidx — one warp per (b,g), coalesced column reads
// ---------------------------------------------------------------------------
__global__ void __launch_bounds__(256)
mq_kernel(float* __restrict__ out_mq)
{
    const int wg   = blockIdx.x * 8 + (threadIdx.x >> 5);
    const int lane = threadIdx.x & 31;
    if (wg >= BN * GN) return;
    const int b = wg / GN, g = wg % GN;
    const float* col = g_costT[b][g];
    const unsigned* rb = g_rowbits[b];

    float bv = INFINITY; int bi = 0x7fffffff;
    for (int q = lane; q < QN; q += 32) {
        if ((rb[q * 4 + (g >> 5)] >> (g & 31)) & 1u) {
            float v = apply_adds(col[q], g_addc[b][q]);
            if (v < bv || (v == bv && q < bi)) { bv = v; bi = q; }
        }
    }
    for (int off = 16; off; off >>= 1) {
        float ov = __shfl_xor_sync(0xffffffffu, bv, off);
        int   oi = __shfl_xor_sync(0xffffffffu, bi, off);
        if (ov < bv || (ov == bv && oi < bi)) { bv = ov; bi = oi; }
    }
    if (lane == 0)
        out_mq[(size_t)b * GN + g] = (bi == 0x7fffffff) ? 0.0f : (float)bi;
}

// ---------------------------------------------------------------------------
extern "C" void kernel_launch(void* const* d_in, const int* in_sizes, int n_in,
                              void* d_out, int out_size)
{
    const float* l1  = (const float*)d_in[0];
    const float* l2  = (const float*)d_in[1];
    const float* l3  = (const float*)d_in[2];
    const float* pb  = (const float*)d_in[3];
    const float* gb  = (const float*)d_in[4];
    const float* isz = (const float*)d_in[5];
    const int*   t1  = (const int*)d_in[6];
    const int*   t2  = (const int*)d_in[7];
    const int*   t3  = (const int*)d_in[8];

    float* out = (float*)d_out;
    float* o_m    = out;
    float* o_sel  = o_m   + (size_t)BN * QN * GN;
    float* o_gti  = o_sel + (size_t)BN * QN;
    float* o_mq   = o_gti + (size_t)BN * QN;
    float* o_cost = o_mq  + (size_t)BN * GN;

    dim3 grid1((QN + 127) / 128, BN);
    cost_kernel<<<grid1, 128>>>(l1, l2, l3, pb, gb, isz, t1, t2, t3, o_cost);

    topk_kernel<<<(BN * GN + 7) / 8, 256>>>(pb, gb);

    const int smem = QN * 4 * 4      // rowbits
                   + QN * 2          // stamp
                   + QN * 4          // fillcnt
                   + (GN + GN) * 4   // colc, unm
                   + 128 * 4         // flist
                   + 512 * 4         // conf
                   + 16;             // cnt
    cudaFuncSetAttribute(match_core, cudaFuncAttributeMaxDynamicSharedMemorySize, smem);
    match_core<<<BN, TPB, smem>>>(o_cost);

    expand_kernel<<<2048, 256>>>(o_m, o_sel, o_gti);
    mq_kernel<<<(BN * GN + 7) / 8, 256>>>(o_mq);
}